// round 1
// baseline (speedup 1.0000x reference)
#include <cuda_runtime.h>
#include <cuda_bf16.h>
#include <math.h>

// Problem constants
#define S_LEN 2048
#define HID   2048
#define NH    16
#define HD    128
#define QKV_N 6144   // 3*HID
#define EPS   1e-5f

// ---------------- scratch (device globals: allocation-free) ----------------
__device__ float g_lnx  [S_LEN * HID];    // 16 MB
__device__ float g_mixed[S_LEN * QKV_N];  // 48 MB
__device__ float g_ctx  [S_LEN * HID];    // 16 MB

// ---------------- LayerNorm: one block per row ----------------
__global__ __launch_bounds__(256)
void layernorm_kernel(const float* __restrict__ x,
                      const float* __restrict__ w,
                      const float* __restrict__ b) {
    int s = blockIdx.x;
    int tid = threadIdx.x;
    const float* row = x + (size_t)s * HID;

    // 2048 floats / 256 threads = 8 each, as two coalesced float4 halves
    float4 a = *(const float4*)(row + tid * 4);
    float4 c = *(const float4*)(row + 1024 + tid * 4);

    float s1 = a.x + a.y + a.z + a.w + c.x + c.y + c.z + c.w;
    float s2 = a.x*a.x + a.y*a.y + a.z*a.z + a.w*a.w
             + c.x*c.x + c.y*c.y + c.z*c.z + c.w*c.w;

    #pragma unroll
    for (int off = 16; off; off >>= 1) {
        s1 += __shfl_xor_sync(0xffffffffu, s1, off);
        s2 += __shfl_xor_sync(0xffffffffu, s2, off);
    }
    __shared__ float r1[8], r2[8];
    int wrp = tid >> 5, lane = tid & 31;
    if (lane == 0) { r1[wrp] = s1; r2[wrp] = s2; }
    __syncthreads();
    if (tid == 0) {
        float t1 = 0.f, t2 = 0.f;
        #pragma unroll
        for (int i = 0; i < 8; i++) { t1 += r1[i]; t2 += r2[i]; }
        r1[0] = t1; r2[0] = t2;
    }
    __syncthreads();
    float mu  = r1[0] * (1.f / HID);
    float var = r2[0] * (1.f / HID) - mu * mu;
    float rs  = rsqrtf(var + EPS);

    float* yrow = g_lnx + (size_t)s * HID;
    int c0 = tid * 4;
    float4 w0 = *(const float4*)(w + c0);
    float4 b0 = *(const float4*)(b + c0);
    float4 o0;
    o0.x = (a.x - mu) * rs * w0.x + b0.x;
    o0.y = (a.y - mu) * rs * w0.y + b0.y;
    o0.z = (a.z - mu) * rs * w0.z + b0.z;
    o0.w = (a.w - mu) * rs * w0.w + b0.w;
    *(float4*)(yrow + c0) = o0;

    int c1 = 1024 + tid * 4;
    float4 w1 = *(const float4*)(w + c1);
    float4 b1 = *(const float4*)(b + c1);
    float4 o1;
    o1.x = (c.x - mu) * rs * w1.x + b1.x;
    o1.y = (c.y - mu) * rs * w1.y + b1.y;
    o1.z = (c.z - mu) * rs * w1.z + b1.z;
    o1.w = (c.w - mu) * rs * w1.w + b1.w;
    *(float4*)(yrow + c1) = o1;
}

// ---------------- NT SGEMM: C[M,N] = A[M,K] * B[N,K]^T + bias ----------------
// BM=BN=128, BK=8, 256 threads, 8x8 micro-tile per thread.
template<int N, int K>
__device__ __forceinline__
void gemm_body(const float* __restrict__ A, const float* __restrict__ B,
               const float* __restrict__ bias, float* __restrict__ C) {
    __shared__ float As[8][132];
    __shared__ float Bs[8][132];

    int tid  = threadIdx.x;
    int row0 = blockIdx.y * 128;
    int col0 = blockIdx.x * 128;

    int lr = tid >> 1;            // 0..127
    int lc = (tid & 1) * 4;       // 0 or 4
    const float* Aptr = A + (size_t)(row0 + lr) * K + lc;
    const float* Bptr = B + (size_t)(col0 + lr) * K + lc;

    int tx = tid & 15, ty = tid >> 4;

    float acc[8][8];
    #pragma unroll
    for (int i = 0; i < 8; i++)
        #pragma unroll
        for (int j = 0; j < 8; j++) acc[i][j] = 0.f;

    for (int k0 = 0; k0 < K; k0 += 8) {
        float4 av = *(const float4*)(Aptr + k0);
        float4 bv = *(const float4*)(Bptr + k0);
        As[lc+0][lr] = av.x; As[lc+1][lr] = av.y;
        As[lc+2][lr] = av.z; As[lc+3][lr] = av.w;
        Bs[lc+0][lr] = bv.x; Bs[lc+1][lr] = bv.y;
        Bs[lc+2][lr] = bv.z; Bs[lc+3][lr] = bv.w;
        __syncthreads();

        #pragma unroll
        for (int k = 0; k < 8; k++) {
            float a_frag[8], b_frag[8];
            #pragma unroll
            for (int i = 0; i < 8; i++) a_frag[i] = As[k][ty * 8 + i];
            #pragma unroll
            for (int j = 0; j < 8; j++) b_frag[j] = Bs[k][tx * 8 + j];
            #pragma unroll
            for (int i = 0; i < 8; i++)
                #pragma unroll
                for (int j = 0; j < 8; j++)
                    acc[i][j] += a_frag[i] * b_frag[j];
        }
        __syncthreads();
    }

    #pragma unroll
    for (int i = 0; i < 8; i++) {
        float* crow = C + (size_t)(row0 + ty * 8 + i) * N + col0 + tx * 8;
        #pragma unroll
        for (int j = 0; j < 8; j += 4) {
            int cg = col0 + tx * 8 + j;
            float4 v;
            v.x = acc[i][j+0] + bias[cg+0];
            v.y = acc[i][j+1] + bias[cg+1];
            v.z = acc[i][j+2] + bias[cg+2];
            v.w = acc[i][j+3] + bias[cg+3];
            *(float4*)(crow + j) = v;
        }
    }
}

__global__ __launch_bounds__(256)
void gemm_qkv_kernel(const float* __restrict__ W, const float* __restrict__ bias) {
    gemm_body<QKV_N, HID>(g_lnx, W, bias, g_mixed);
}

__global__ __launch_bounds__(256)
void gemm_proj_kernel(const float* __restrict__ W, const float* __restrict__ bias,
                      float* __restrict__ out) {
    gemm_body<HID, HID>(g_ctx, W, bias, out);
}

// ---------------- causal flash attention (fp32, registers) ----------------
// Grid: (S/64, NH). 256 threads. Thread t: query row m = t>>2, d-part p = t&3.
// Ownership of d is strided: d = i*16 + p*4 + k (i in 0..7, k in 0..3)
// -> conflict-free smem reads (4 distinct 16B segments per 64B + m-broadcast),
//    static register indexing.
#define AM 64
#define AN 32

__global__ __launch_bounds__(256)
void attn_kernel() {
    __shared__ float Ks[AN][HD];
    __shared__ float Vs[AN][HD];

    int h   = blockIdx.y;
    int q0  = blockIdx.x * AM;
    int tid = threadIdx.x;
    int m   = tid >> 2;
    int p   = tid & 3;
    int qi  = q0 + m;

    const float scale = 0.08838834764831845f;  // 1/sqrt(128)

    float q[32], o[32];
    const float* qptr = g_mixed + (size_t)qi * QKV_N + h * HD + p * 4;
    #pragma unroll
    for (int i = 0; i < 8; i++) {
        float4 v = *(const float4*)(qptr + i * 16);
        q[i*4+0] = v.x * scale; q[i*4+1] = v.y * scale;
        q[i*4+2] = v.z * scale; q[i*4+3] = v.w * scale;
        o[i*4+0] = 0.f; o[i*4+1] = 0.f; o[i*4+2] = 0.f; o[i*4+3] = 0.f;
    }

    float m_i = -INFINITY, l_i = 0.f;

    // tile loaders: thread t loads row r = t>>3, 16 floats at col (t&7)*16
    int lrow = tid >> 3;
    int lcol = (tid & 7) * 16;

    int kend = q0 + AM;  // exclusive causal bound at tile granularity
    for (int kt0 = 0; kt0 < kend; kt0 += AN) {
        const float* kp = g_mixed + (size_t)(kt0 + lrow) * QKV_N + HID + h * HD + lcol;
        const float* vp = kp + HID;  // V lives HID further along the row
        #pragma unroll
        for (int j = 0; j < 4; j++) {
            *(float4*)&Ks[lrow][lcol + j * 4] = *(const float4*)(kp + j * 4);
            *(float4*)&Vs[lrow][lcol + j * 4] = *(const float4*)(vp + j * 4);
        }
        __syncthreads();

        // scores
        float sc[AN];
        #pragma unroll
        for (int n = 0; n < AN; n++) {
            float part = 0.f;
            #pragma unroll
            for (int i = 0; i < 8; i++) {
                float4 kv = *(const float4*)&Ks[n][i * 16 + p * 4];
                part += q[i*4+0] * kv.x + q[i*4+1] * kv.y
                      + q[i*4+2] * kv.z + q[i*4+3] * kv.w;
            }
            part += __shfl_xor_sync(0xffffffffu, part, 1);
            part += __shfl_xor_sync(0xffffffffu, part, 2);
            sc[n] = (kt0 + n <= qi) ? part : -INFINITY;
        }

        // online softmax update
        float tmax = m_i;
        #pragma unroll
        for (int n = 0; n < AN; n++) tmax = fmaxf(tmax, sc[n]);
        float corr = __expf(m_i - tmax);
        m_i = tmax;
        float ps = 0.f;
        #pragma unroll
        for (int n = 0; n < AN; n++) { sc[n] = __expf(sc[n] - m_i); ps += sc[n]; }
        l_i = l_i * corr + ps;

        #pragma unroll
        for (int ii = 0; ii < 32; ii++) o[ii] *= corr;

        // O += P * V
        #pragma unroll
        for (int n = 0; n < AN; n++) {
            float pn = sc[n];
            #pragma unroll
            for (int i = 0; i < 8; i++) {
                float4 vv = *(const float4*)&Vs[n][i * 16 + p * 4];
                o[i*4+0] += pn * vv.x; o[i*4+1] += pn * vv.y;
                o[i*4+2] += pn * vv.z; o[i*4+3] += pn * vv.w;
            }
        }
        __syncthreads();
    }

    float inv = 1.f / l_i;
    float* op = g_ctx + (size_t)qi * HID + h * HD + p * 4;
    #pragma unroll
    for (int i = 0; i < 8; i++) {
        float4 v;
        v.x = o[i*4+0] * inv; v.y = o[i*4+1] * inv;
        v.z = o[i*4+2] * inv; v.w = o[i*4+3] * inv;
        *(float4*)(op + i * 16) = v;
    }
}

// ---------------- launch ----------------
extern "C" void kernel_launch(void* const* d_in, const int* in_sizes, int n_in,
                              void* d_out, int out_size) {
    const float* hs   = (const float*)d_in[0];
    const float* lw   = (const float*)d_in[1];
    const float* lb   = (const float*)d_in[2];
    const float* qkvw = (const float*)d_in[3];
    const float* qkvb = (const float*)d_in[4];
    const float* pw   = (const float*)d_in[5];
    const float* pb   = (const float*)d_in[6];
    float* out = (float*)d_out;

    layernorm_kernel<<<S_LEN, 256>>>(hs, lw, lb);
    gemm_qkv_kernel<<<dim3(QKV_N / 128, S_LEN / 128), 256>>>(qkvw, qkvb);
    attn_kernel<<<dim3(S_LEN / AM, NH), 256>>>();
    gemm_proj_kernel<<<dim3(HID / 128, S_LEN / 128), 256>>>(pw, pb, out);
}

// round 4
// speedup vs baseline: 1.4701x; 1.4701x over previous
#include <cuda_runtime.h>
#include <cuda_bf16.h>
#include <math.h>
#include <stdint.h>

// Problem constants
#define S_LEN 2048
#define HID   2048
#define NH    16
#define HD    128
#define QKV_N 6144   // 3*HID
#define EPS   1e-5f

// ---------------- scratch (device globals: allocation-free) ----------------
__device__ float         g_mixed  [S_LEN * QKV_N];  // fp32 QKV for attention
__device__ __nv_bfloat16 g_lnx_hi [S_LEN * HID];
__device__ __nv_bfloat16 g_lnx_lo [S_LEN * HID];
__device__ __nv_bfloat16 g_wqkv_hi[QKV_N * HID];
__device__ __nv_bfloat16 g_wqkv_lo[QKV_N * HID];
__device__ __nv_bfloat16 g_ctx_hi [S_LEN * HID];
__device__ __nv_bfloat16 g_ctx_lo [S_LEN * HID];
__device__ __nv_bfloat16 g_wproj_hi[HID * HID];
__device__ __nv_bfloat16 g_wproj_lo[HID * HID];

// ---------------- helpers ----------------
__device__ __forceinline__ uint32_t smem_u32(const void* p) {
    uint32_t a;
    asm("{ .reg .u64 t; cvta.to.shared.u64 t, %1; cvt.u32.u64 %0, t; }" : "=r"(a) : "l"(p));
    return a;
}
__device__ __forceinline__ void ldm_x4(uint32_t* r, uint32_t addr) {
    asm volatile("ldmatrix.sync.aligned.m8n8.x4.shared.b16 {%0,%1,%2,%3}, [%4];"
        : "=r"(r[0]), "=r"(r[1]), "=r"(r[2]), "=r"(r[3]) : "r"(addr));
}
__device__ __forceinline__ void mma_bf16(float* d, const uint32_t* a, uint32_t b0, uint32_t b1) {
    asm volatile("mma.sync.aligned.m16n8k16.row.col.f32.bf16.bf16.f32 "
        "{%0,%1,%2,%3}, {%4,%5,%6,%7}, {%8,%9}, {%0,%1,%2,%3};"
        : "+f"(d[0]), "+f"(d[1]), "+f"(d[2]), "+f"(d[3])
        : "r"(a[0]), "r"(a[1]), "r"(a[2]), "r"(a[3]), "r"(b0), "r"(b1));
}
__device__ __forceinline__ void cp16(uint32_t saddr, const void* g) {
    asm volatile("cp.async.cg.shared.global [%0], [%1], 16;" :: "r"(saddr), "l"(g));
}
#define CP_COMMIT() asm volatile("cp.async.commit_group;" ::: "memory")
#define CP_WAIT1()  asm volatile("cp.async.wait_group 1;" ::: "memory")
#define CP_WAIT0()  asm volatile("cp.async.wait_group 0;" ::: "memory")

// ---------------- fp32 -> bf16 hi/lo split helpers ----------------
__device__ __forceinline__ void split4_store(float4 v, __nv_bfloat16* hp, __nv_bfloat16* lp) {
    __nv_bfloat16 h0 = __float2bfloat16(v.x), h1 = __float2bfloat16(v.y);
    __nv_bfloat16 h2 = __float2bfloat16(v.z), h3 = __float2bfloat16(v.w);
    __nv_bfloat16 l0 = __float2bfloat16(v.x - __bfloat162float(h0));
    __nv_bfloat16 l1 = __float2bfloat16(v.y - __bfloat162float(h1));
    __nv_bfloat16 l2 = __float2bfloat16(v.z - __bfloat162float(h2));
    __nv_bfloat16 l3 = __float2bfloat16(v.w - __bfloat162float(h3));
    __nv_bfloat162 H0 = __halves2bfloat162(h0, h1), H1 = __halves2bfloat162(h2, h3);
    __nv_bfloat162 L0 = __halves2bfloat162(l0, l1), L1 = __halves2bfloat162(l2, l3);
    *(uint2*)hp = make_uint2(*(uint32_t*)&H0, *(uint32_t*)&H1);
    *(uint2*)lp = make_uint2(*(uint32_t*)&L0, *(uint32_t*)&L1);
}

// ---------------- LayerNorm: one block per row, writes bf16 hi/lo ----------------
__global__ __launch_bounds__(256)
void layernorm_kernel(const float* __restrict__ x,
                      const float* __restrict__ w,
                      const float* __restrict__ b) {
    int s = blockIdx.x;
    int tid = threadIdx.x;
    const float* row = x + (size_t)s * HID;

    float4 a = *(const float4*)(row + tid * 4);
    float4 c = *(const float4*)(row + 1024 + tid * 4);

    float s1 = a.x + a.y + a.z + a.w + c.x + c.y + c.z + c.w;
    float s2 = a.x*a.x + a.y*a.y + a.z*a.z + a.w*a.w
             + c.x*c.x + c.y*c.y + c.z*c.z + c.w*c.w;

    #pragma unroll
    for (int off = 16; off; off >>= 1) {
        s1 += __shfl_xor_sync(0xffffffffu, s1, off);
        s2 += __shfl_xor_sync(0xffffffffu, s2, off);
    }
    __shared__ float r1[8], r2[8];
    int wrp = tid >> 5, lane = tid & 31;
    if (lane == 0) { r1[wrp] = s1; r2[wrp] = s2; }
    __syncthreads();
    if (tid == 0) {
        float t1 = 0.f, t2 = 0.f;
        #pragma unroll
        for (int i = 0; i < 8; i++) { t1 += r1[i]; t2 += r2[i]; }
        r1[0] = t1; r2[0] = t2;
    }
    __syncthreads();
    float mu  = r1[0] * (1.f / HID);
    float var = r2[0] * (1.f / HID) - mu * mu;
    float rs  = rsqrtf(var + EPS);

    size_t rbase = (size_t)s * HID;
    int c0 = tid * 4;
    float4 w0 = *(const float4*)(w + c0);
    float4 b0 = *(const float4*)(b + c0);
    float4 o0;
    o0.x = (a.x - mu) * rs * w0.x + b0.x;
    o0.y = (a.y - mu) * rs * w0.y + b0.y;
    o0.z = (a.z - mu) * rs * w0.z + b0.z;
    o0.w = (a.w - mu) * rs * w0.w + b0.w;
    split4_store(o0, g_lnx_hi + rbase + c0, g_lnx_lo + rbase + c0);

    int c1 = 1024 + tid * 4;
    float4 w1 = *(const float4*)(w + c1);
    float4 b1 = *(const float4*)(b + c1);
    float4 o1;
    o1.x = (c.x - mu) * rs * w1.x + b1.x;
    o1.y = (c.y - mu) * rs * w1.y + b1.y;
    o1.z = (c.z - mu) * rs * w1.z + b1.z;
    o1.w = (c.w - mu) * rs * w1.w + b1.w;
    split4_store(o1, g_lnx_hi + rbase + c1, g_lnx_lo + rbase + c1);
}

// ---------------- weight split kernel ----------------
__global__ __launch_bounds__(256)
void splitw_kernel(const float* __restrict__ x, int which, int n) {
    __nv_bfloat16* hi = which ? g_wproj_hi : g_wqkv_hi;
    __nv_bfloat16* lo = which ? g_wproj_lo : g_wqkv_lo;
    int i = (blockIdx.x * 256 + threadIdx.x) * 4;
    if (i < n) {
        float4 v = *(const float4*)(x + i);
        split4_store(v, hi + i, lo + i);
    }
}

// ---------------- mma.sync bf16x3 GEMM: C[M,N] = A[M,K]*B[N,K]^T + bias ------
// CTA tile 128x128, BK=32. 8 warps, each 64x32 (4 mtiles x 4 n8-tiles).
// Smem per stage: A-hi 8KB | A-lo 8KB | B-hi 8KB | B-lo 8KB = 32KB. 2 stages.
// Each 8KB region: 128 rows x 32 cols bf16 as 16x16 tiles (512B each):
//   off = ((r>>4)*2 + (c>>4))*512 + (r&15)*32 + (((c>>3)&1) ^ ((r>>2)&1))*16 + (c&7)*2
#define BK 32
#define STAGE_BYTES 32768
#define A_HI_OFF 0
#define A_LO_OFF 8192
#define B_HI_OFF 16384
#define B_LO_OFF 24576
#define GSMEM (2 * STAGE_BYTES)

__global__ __launch_bounds__(256, 1)
void gemm_mma_kernel(int which, const float* __restrict__ bias,
                     float* __restrict__ Cout, int ldc) {
    extern __shared__ __align__(1024) char smem[];
    const __nv_bfloat16 *Ahi, *Alo, *Bhi, *Blo;
    float* Cp;
    if (which == 0) { Ahi = g_lnx_hi; Alo = g_lnx_lo; Bhi = g_wqkv_hi; Blo = g_wqkv_lo; Cp = g_mixed; }
    else            { Ahi = g_ctx_hi; Alo = g_ctx_lo; Bhi = g_wproj_hi; Blo = g_wproj_lo; Cp = Cout; }

    const int NCHUNK = HID / BK;  // 64
    uint32_t sb = smem_u32(smem);
    int tid = threadIdx.x, wid = tid >> 5, lane = tid & 31;
    int row0 = blockIdx.y * 128, col0 = blockIdx.x * 128;
    int wm = wid >> 2, wn = wid & 3;

    // cp.async mapping: 512 16B-chunks per 8KB region; thread handles v = tid, tid+256
    // v -> row r = v>>2 (0..127), 16B-chunk c16 = v&3 (k-offset c16*8)
    int soff[2]; size_t ga[2], gb[2];
    #pragma unroll
    for (int j = 0; j < 2; j++) {
        int v = tid + j * 256;
        int r = v >> 2, c16 = v & 3, tr = r & 15;
        soff[j] = ((r >> 4) * 2 + (c16 >> 1)) * 512 + tr * 32
                + (((c16 & 1) ^ ((tr >> 2) & 1))) * 16;
        ga[j] = (size_t)(row0 + r) * HID + c16 * 8;
        gb[j] = (size_t)(col0 + r) * HID + c16 * 8;
    }

    float acc[4][4][4];
    #pragma unroll
    for (int i = 0; i < 4; i++)
        #pragma unroll
        for (int j = 0; j < 4; j++)
            #pragma unroll
            for (int q = 0; q < 4; q++) acc[i][j][q] = 0.f;

    // ldmatrix per-lane address offset within a 512B 16x16 tile
    int lr = lane & 15, lch = lane >> 4;
    int laneoff = lr * 32 + ((lch ^ ((lr >> 2) & 1))) * 16;

    // prologue: issue chunks 0 and 1
    #pragma unroll
    for (int c = 0; c < 2; c++) {
        uint32_t base = sb + c * STAGE_BYTES;
        int k0 = c * BK;
        #pragma unroll
        for (int j = 0; j < 2; j++) {
            cp16(base + A_HI_OFF + soff[j], Ahi + ga[j] + k0);
            cp16(base + A_LO_OFF + soff[j], Alo + ga[j] + k0);
            cp16(base + B_HI_OFF + soff[j], Bhi + gb[j] + k0);
            cp16(base + B_LO_OFF + soff[j], Blo + gb[j] + k0);
        }
        CP_COMMIT();
    }

    for (int c = 0; c < NCHUNK; c++) {
        if (c >= NCHUNK - 2) CP_WAIT0(); else CP_WAIT1();
        __syncthreads();
        uint32_t stg = sb + (c & 1) * STAGE_BYTES;

        #pragma unroll
        for (int kt = 0; kt < 2; kt++) {
            uint32_t aT0 = stg + ((wm * 4 + 0) * 2 + kt) * 512 + laneoff;
            uint32_t bT0 = stg + ((wn * 2 + 0) * 2 + kt) * 512 + laneoff;
            uint32_t aH[4][4], aL[4][4], bH[2][4], bL[2][4];
            #pragma unroll
            for (int mt = 0; mt < 4; mt++) ldm_x4(aH[mt], aT0 + A_HI_OFF + mt * 1024);
            #pragma unroll
            for (int j = 0; j < 2; j++)  ldm_x4(bH[j], bT0 + B_HI_OFF + j * 1024);
            // Ah * Bh
            #pragma unroll
            for (int mt = 0; mt < 4; mt++)
                #pragma unroll
                for (int j = 0; j < 2; j++) {
                    mma_bf16(acc[mt][j*2+0], aH[mt], bH[j][0], bH[j][2]);
                    mma_bf16(acc[mt][j*2+1], aH[mt], bH[j][1], bH[j][3]);
                }
            // Ah * Bl
            #pragma unroll
            for (int j = 0; j < 2; j++)  ldm_x4(bL[j], bT0 + B_LO_OFF + j * 1024);
            #pragma unroll
            for (int mt = 0; mt < 4; mt++)
                #pragma unroll
                for (int j = 0; j < 2; j++) {
                    mma_bf16(acc[mt][j*2+0], aH[mt], bL[j][0], bL[j][2]);
                    mma_bf16(acc[mt][j*2+1], aH[mt], bL[j][1], bL[j][3]);
                }
            // Al * Bh
            #pragma unroll
            for (int mt = 0; mt < 4; mt++) ldm_x4(aL[mt], aT0 + A_LO_OFF + mt * 1024);
            #pragma unroll
            for (int mt = 0; mt < 4; mt++)
                #pragma unroll
                for (int j = 0; j < 2; j++) {
                    mma_bf16(acc[mt][j*2+0], aL[mt], bH[j][0], bH[j][2]);
                    mma_bf16(acc[mt][j*2+1], aL[mt], bH[j][1], bH[j][3]);
                }
        }
        __syncthreads();
        if (c + 2 < NCHUNK) {
            uint32_t base = sb + (c & 1) * STAGE_BYTES;
            int k0 = (c + 2) * BK;
            #pragma unroll
            for (int j = 0; j < 2; j++) {
                cp16(base + A_HI_OFF + soff[j], Ahi + ga[j] + k0);
                cp16(base + A_LO_OFF + soff[j], Alo + ga[j] + k0);
                cp16(base + B_HI_OFF + soff[j], Bhi + gb[j] + k0);
                cp16(base + B_LO_OFF + soff[j], Blo + gb[j] + k0);
            }
            CP_COMMIT();
        }
    }

    // epilogue: fragment (lane l): rows rg, rg+8; cols cg, cg+1 per n8 tile
    int rg = lane >> 2, cg = (lane & 3) * 2;
    #pragma unroll
    for (int mt = 0; mt < 4; mt++) {
        int row = row0 + wm * 64 + mt * 16 + rg;
        #pragma unroll
        for (int n8 = 0; n8 < 4; n8++) {
            int col = col0 + wn * 32 + n8 * 8 + cg;
            float b0 = bias[col], b1 = bias[col + 1];
            float2 v0 = make_float2(acc[mt][n8][0] + b0, acc[mt][n8][1] + b1);
            float2 v1 = make_float2(acc[mt][n8][2] + b0, acc[mt][n8][3] + b1);
            *(float2*)(Cp + (size_t)row * ldc + col)       = v0;
            *(float2*)(Cp + (size_t)(row + 8) * ldc + col) = v1;
        }
    }
}

// ---------------- causal flash attention (fp32, registers) ----------------
#define AM 64
#define AN 32

__global__ __launch_bounds__(256)
void attn_kernel() {
    __shared__ float Ks[AN][HD];
    __shared__ float Vs[AN][HD];

    int h   = blockIdx.y;
    int q0  = blockIdx.x * AM;
    int tid = threadIdx.x;
    int m   = tid >> 2;
    int p   = tid & 3;
    int qi  = q0 + m;

    const float scale = 0.08838834764831845f;  // 1/sqrt(128)

    float q[32], o[32];
    const float* qptr = g_mixed + (size_t)qi * QKV_N + h * HD + p * 4;
    #pragma unroll
    for (int i = 0; i < 8; i++) {
        float4 v = *(const float4*)(qptr + i * 16);
        q[i*4+0] = v.x * scale; q[i*4+1] = v.y * scale;
        q[i*4+2] = v.z * scale; q[i*4+3] = v.w * scale;
        o[i*4+0] = 0.f; o[i*4+1] = 0.f; o[i*4+2] = 0.f; o[i*4+3] = 0.f;
    }

    float m_i = -INFINITY, l_i = 0.f;

    int lrow = tid >> 3;
    int lcol = (tid & 7) * 16;

    int kend = q0 + AM;
    for (int kt0 = 0; kt0 < kend; kt0 += AN) {
        const float* kp = g_mixed + (size_t)(kt0 + lrow) * QKV_N + HID + h * HD + lcol;
        const float* vp = kp + HID;
        #pragma unroll
        for (int j = 0; j < 4; j++) {
            *(float4*)&Ks[lrow][lcol + j * 4] = *(const float4*)(kp + j * 4);
            *(float4*)&Vs[lrow][lcol + j * 4] = *(const float4*)(vp + j * 4);
        }
        __syncthreads();

        float sc[AN];
        #pragma unroll
        for (int n = 0; n < AN; n++) {
            float part = 0.f;
            #pragma unroll
            for (int i = 0; i < 8; i++) {
                float4 kv = *(const float4*)&Ks[n][i * 16 + p * 4];
                part += q[i*4+0] * kv.x + q[i*4+1] * kv.y
                      + q[i*4+2] * kv.z + q[i*4+3] * kv.w;
            }
            part += __shfl_xor_sync(0xffffffffu, part, 1);
            part += __shfl_xor_sync(0xffffffffu, part, 2);
            sc[n] = (kt0 + n <= qi) ? part : -INFINITY;
        }

        float tmax = m_i;
        #pragma unroll
        for (int n = 0; n < AN; n++) tmax = fmaxf(tmax, sc[n]);
        float corr = __expf(m_i - tmax);
        m_i = tmax;
        float ps = 0.f;
        #pragma unroll
        for (int n = 0; n < AN; n++) { sc[n] = __expf(sc[n] - m_i); ps += sc[n]; }
        l_i = l_i * corr + ps;

        #pragma unroll
        for (int ii = 0; ii < 32; ii++) o[ii] *= corr;

        #pragma unroll
        for (int n = 0; n < AN; n++) {
            float pn = sc[n];
            #pragma unroll
            for (int i = 0; i < 8; i++) {
                float4 vv = *(const float4*)&Vs[n][i * 16 + p * 4];
                o[i*4+0] += pn * vv.x; o[i*4+1] += pn * vv.y;
                o[i*4+2] += pn * vv.z; o[i*4+3] += pn * vv.w;
            }
        }
        __syncthreads();
    }

    float inv = 1.f / l_i;
    size_t obase = (size_t)qi * HID + h * HD + p * 4;
    #pragma unroll
    for (int i = 0; i < 8; i++) {
        float4 v;
        v.x = o[i*4+0] * inv; v.y = o[i*4+1] * inv;
        v.z = o[i*4+2] * inv; v.w = o[i*4+3] * inv;
        split4_store(v, g_ctx_hi + obase + i * 16, g_ctx_lo + obase + i * 16);
    }
}

// ---------------- launch ----------------
extern "C" void kernel_launch(void* const* d_in, const int* in_sizes, int n_in,
                              void* d_out, int out_size) {
    const float* hs   = (const float*)d_in[0];
    const float* lw   = (const float*)d_in[1];
    const float* lb   = (const float*)d_in[2];
    const float* qkvw = (const float*)d_in[3];
    const float* qkvb = (const float*)d_in[4];
    const float* pw   = (const float*)d_in[5];
    const float* pb   = (const float*)d_in[6];
    float* out = (float*)d_out;

    cudaFuncSetAttribute(gemm_mma_kernel, cudaFuncAttributeMaxDynamicSharedMemorySize, GSMEM);

    layernorm_kernel<<<S_LEN, 256>>>(hs, lw, lb);
    splitw_kernel<<<(QKV_N * HID / 4) / 256, 256>>>(qkvw, 0, QKV_N * HID);
    splitw_kernel<<<(HID * HID / 4) / 256, 256>>>(pw, 1, HID * HID);
    gemm_mma_kernel<<<dim3(QKV_N / 128, S_LEN / 128), 256, GSMEM>>>(0, qkvb, nullptr, QKV_N);
    attn_kernel<<<dim3(S_LEN / AM, NH), 256>>>();
    gemm_mma_kernel<<<dim3(HID / 128, S_LEN / 128), 256, GSMEM>>>(1, pb, out, HID);
}